// round 7
// baseline (speedup 1.0000x reference)
#include <cuda_runtime.h>

#define BH_TOTAL (1024 * 32)
#define NNB  25
#define FDIM 128
#define DDIM 128
#define NTHREADS 512
#define GRID 296          // 2 CTAs/SM target
#define BATCH 64          // xagg rows per CTA batch
#define PER_WARP 4        // bh per warp per batch (16 warps * 4 = 64)
#define NJMAX 111         // max tiles per CTA (ceil(32768/296))

__device__ __align__(16) float g_u_self[FDIM];
__device__ __align__(16) float g_u_neigh[FDIM];

__global__ void precompute_u_kernel(const float* __restrict__ w,
                                    const float* __restrict__ a_self,
                                    const float* __restrict__ a_neigh) {
    int t = threadIdx.x;
    if (t < FDIM) {
        float s = 0.f;
        #pragma unroll 8
        for (int d = 0; d < DDIM; d++) s = fmaf(w[t * DDIM + d], a_self[d], s);
        g_u_self[t] = s;
    } else if (t < 2 * FDIM) {
        int f = t - FDIM;
        float s = 0.f;
        #pragma unroll 8
        for (int d = 0; d < DDIM; d++) s = fmaf(w[f * DDIM + d], a_neigh[d], s);
        g_u_neigh[f] = s;
    }
}

__device__ __forceinline__ float dot4(float4 a, float4 b) {
    float s = a.x * b.x;
    s = fmaf(a.y, b.y, s);
    s = fmaf(a.z, b.z, s);
    s = fmaf(a.w, b.w, s);
    return s;
}
__device__ __forceinline__ float xor_reduce(float v) {
    #pragma unroll
    for (int o = 16; o; o >>= 1)
        v += __shfl_xor_sync(0xffffffffu, v, o);
    return v;
}

__global__ __launch_bounds__(NTHREADS, 2)
void gat_agg_kernel(const float* __restrict__ x_self,
                    const float* __restrict__ x_neigh,
                    const float* __restrict__ w,
                    float* __restrict__ out) {
    __shared__ __align__(16) float xagg_sm[BATCH][FDIM];   // 32 KB

    const int tid   = threadIdx.x;
    const int lane  = tid & 31;
    const int warp  = tid >> 5;
    const int g     = lane & 3;        // f-group within nibble
    const int d_own = tid >> 2;        // output column (0..127)

    // W slice in registers: wreg[i] = W[32*g + i][d_own]
    float wreg[32];
    #pragma unroll
    for (int i = 0; i < 32; i++)
        wreg[i] = w[(32 * g + i) * DDIM + d_own];

    const float4 un4 = ((const float4*)g_u_neigh)[lane];
    const float4 us4 = ((const float4*)g_u_self)[lane];

    const int cta = blockIdx.x;

    for (int jb = 0; jb < NJMAX; jb += BATCH) {
        // ================= Phase A: warp-autonomous tiles =================
        #pragma unroll 1
        for (int e = 0; e < PER_WARP; e++) {
            const int slot = warp * PER_WARP + e;
            const long bh = (long)cta + (long)(jb + slot) * GRID;
            if (bh >= BH_TOTAL) break;

            const float4* s4 = (const float4*)(x_self  + bh * FDIM);
            const float4* n4 = (const float4*)(x_neigh + bh * (NNB * FDIM));

            // ---- pass 1: scores ----
            const float4 selfv = s4[lane];
            float pss = xor_reduce(dot4(selfv, us4));   // x_self . u_self (all lanes)
            float psn = xor_reduce(dot4(selfv, un4));   // x_self . u_neigh
            float sv = (lane == 0) ? psn : 0.f;         // lane k holds entry-k dot
            #pragma unroll
            for (int k = 0; k < NNB; k++) {
                float p = xor_reduce(dot4(n4[k * 32 + lane], un4));
                if (lane == k + 1) sv = p;
            }

            // ---- softmax over 26 entries, in-warp ----
            float v = (lane < 26) ? (pss + sv) : -3.0e38f;
            v = (v > 0.f) ? v : 0.2f * v;               // leaky_relu(0.2)
            float m = v;
            #pragma unroll
            for (int o = 16; o; o >>= 1)
                m = fmaxf(m, __shfl_xor_sync(0xffffffffu, m, o));
            float ex = (lane < 26) ? __expf(v - m) : 0.f;
            const float inv = 1.f / xor_reduce(ex);
            const float attn = ex * inv;                // lane k: weight k

            // ---- pass 2: weighted aggregate (rows re-hit L1/L2) ----
            const float w0 = __shfl_sync(0xffffffffu, attn, 0);
            float4 agg;
            agg.x = w0 * selfv.x; agg.y = w0 * selfv.y;
            agg.z = w0 * selfv.z; agg.w = w0 * selfv.w;
            #pragma unroll
            for (int k = 0; k < NNB; k++) {
                const float wk = __shfl_sync(0xffffffffu, attn, k + 1);
                const float4 xv = n4[k * 32 + lane];
                agg.x = fmaf(wk, xv.x, agg.x);
                agg.y = fmaf(wk, xv.y, agg.y);
                agg.z = fmaf(wk, xv.z, agg.z);
                agg.w = fmaf(wk, xv.w, agg.w);
            }
            ((float4*)xagg_sm[slot])[lane] = agg;
        }
        __syncthreads();

        // ================= Phase B: batched matvec vs register W ==========
        #pragma unroll 1
        for (int r = 0; r < BATCH; r++) {
            const long bh = (long)cta + (long)(jb + r) * GRID;
            if (bh >= BH_TOTAL) break;
            const float4* xa = (const float4*)(xagg_sm[r] + 32 * g);
            float acc = 0.f;
            #pragma unroll
            for (int i = 0; i < 8; i++) {
                const int ii = (i + 2 * g) & 7;         // bank-conflict-free rotation
                const float4 v = xa[ii];
                acc = fmaf(v.x, wreg[4 * ii + 0], acc);
                acc = fmaf(v.y, wreg[4 * ii + 1], acc);
                acc = fmaf(v.z, wreg[4 * ii + 2], acc);
                acc = fmaf(v.w, wreg[4 * ii + 3], acc);
            }
            acc += __shfl_xor_sync(0xffffffffu, acc, 1);
            acc += __shfl_xor_sync(0xffffffffu, acc, 2);
            if (g == 0)
                out[bh * DDIM + d_own] = fmaxf(acc, 0.f);
        }
        __syncthreads();
    }
}

extern "C" void kernel_launch(void* const* d_in, const int* in_sizes, int n_in,
                              void* d_out, int out_size) {
    const float* x_self  = (const float*)d_in[0];
    const float* x_neigh = (const float*)d_in[1];
    const float* w_feat  = (const float*)d_in[2];
    const float* a_self  = (const float*)d_in[3];
    const float* a_neigh = (const float*)d_in[4];
    float* out = (float*)d_out;

    precompute_u_kernel<<<1, 256>>>(w_feat, a_self, a_neigh);
    gat_agg_kernel<<<GRID, NTHREADS>>>(x_self, x_neigh, w_feat, out);
}

// round 11
// speedup vs baseline: 1.0280x; 1.0280x over previous
#include <cuda_runtime.h>

#define BH_TOTAL (1024 * 32)
#define NNB  25
#define KTOT 26
#define FDIM 128
#define DDIM 128
#define NTHREADS 512
#define GRID 296          // 2 CTAs per SM, single wave

#define TILE_BYTES  (KTOT * FDIM * 4)   // 13312
#define SELF_BYTES  (FDIM * 4)          // 512
#define NEIGH_BYTES (NNB * FDIM * 4)    // 12800

__device__ __align__(16) float g_u_self[FDIM];
__device__ __align__(16) float g_u_neigh[FDIM];

__global__ void precompute_u_kernel(const float* __restrict__ w,
                                    const float* __restrict__ a_self,
                                    const float* __restrict__ a_neigh) {
    int t = threadIdx.x;
    if (t < FDIM) {
        float s = 0.f;
        #pragma unroll 8
        for (int d = 0; d < DDIM; d++) s = fmaf(w[t * DDIM + d], a_self[d], s);
        g_u_self[t] = s;
    } else if (t < 2 * FDIM) {
        int f = t - FDIM;
        float s = 0.f;
        #pragma unroll 8
        for (int d = 0; d < DDIM; d++) s = fmaf(w[f * DDIM + d], a_neigh[d], s);
        g_u_neigh[f] = s;
    }
}

// ---- TMA bulk + mbarrier helpers (identical to the proven R3 kernel) ----
__device__ __forceinline__ void mbar_init(unsigned mbar, unsigned count) {
    asm volatile("mbarrier.init.shared.b64 [%0], %1;" :: "r"(mbar), "r"(count) : "memory");
}
__device__ __forceinline__ void mbar_expect_tx(unsigned mbar, unsigned tx) {
    asm volatile("mbarrier.arrive.expect_tx.shared.b64 _, [%0], %1;"
                 :: "r"(mbar), "r"(tx) : "memory");
}
__device__ __forceinline__ void mbar_wait(unsigned mbar, unsigned parity) {
    asm volatile(
        "{\n\t"
        ".reg .pred p;\n\t"
        "WAIT_%=:\n\t"
        "mbarrier.try_wait.parity.acquire.cta.shared::cta.b64 p, [%0], %1, 0x989680;\n\t"
        "@!p bra WAIT_%=;\n\t"
        "}"
        :: "r"(mbar), "r"(parity) : "memory");
}
__device__ __forceinline__ void tma_bulk_g2s(unsigned dst_smem, const void* src_gmem,
                                             unsigned bytes, unsigned mbar) {
    asm volatile(
        "cp.async.bulk.shared::cta.global.mbarrier::complete_tx::bytes [%0], [%1], %2, [%3];"
        :: "r"(dst_smem), "l"(src_gmem), "r"(bytes), "r"(mbar) : "memory");
}
__device__ __forceinline__ void fence_proxy_async_sc() {
    asm volatile("fence.proxy.async.shared::cta;" ::: "memory");
}

__device__ __forceinline__ float dot4(float4 a, float4 b) {
    float s = a.x * b.x;
    s = fmaf(a.y, b.y, s);
    s = fmaf(a.z, b.z, s);
    s = fmaf(a.w, b.w, s);
    return s;
}
__device__ __forceinline__ float xor_reduce(float v) {
    #pragma unroll
    for (int o = 16; o; o >>= 1)
        v += __shfl_xor_sync(0xffffffffu, v, o);
    return v;
}

__global__ __launch_bounds__(NTHREADS, 2)
void gat_agg_kernel(const float* __restrict__ x_self,
                    const float* __restrict__ x_neigh,
                    const float* __restrict__ w,
                    float* __restrict__ out) {
    __shared__ __align__(128) float xs[2][KTOT * FDIM];  // double-buffered tile
    __shared__ __align__(16)  float xagg_sm[FDIM];
    __shared__ float s_raw[32];
    __shared__ __align__(8) unsigned long long mbar[2];

    const int tid   = threadIdx.x;
    const int lane  = tid & 31;
    const int warp  = tid >> 5;
    const int g     = tid & 3;          // f-group / k-group (lane-level)
    const int d_own = tid >> 2;         // output column (0..127)

    // W slice in registers: wreg[i] = W[32*g + i][d_own]
    float wreg[32];
    #pragma unroll
    for (int i = 0; i < 32; i++)
        wreg[i] = w[(32 * g + i) * DDIM + d_own];

    // attention projection vectors in registers (lane-mapped float4)
    const float4 un4 = ((const float4*)g_u_neigh)[lane];
    const float4 us4 = ((const float4*)g_u_self)[lane];

    const unsigned mb0  = (unsigned)__cvta_generic_to_shared(&mbar[0]);
    const unsigned mb1  = (unsigned)__cvta_generic_to_shared(&mbar[1]);
    const unsigned xsa0 = (unsigned)__cvta_generic_to_shared(xs[0]);
    const unsigned xsa1 = (unsigned)__cvta_generic_to_shared(xs[1]);

    if (tid == 0) {
        mbar_init(mb0, 1);
        mbar_init(mb1, 1);
        fence_proxy_async_sc();
    }
    __syncthreads();

    long bh = blockIdx.x;
    // ---- Prologue: TMA tile 0 into buffer 0 ----
    if (tid == 0) {
        mbar_expect_tx(mb0, TILE_BYTES);
        tma_bulk_g2s(xsa0, x_self + bh * FDIM, SELF_BYTES, mb0);
        tma_bulk_g2s(xsa0 + SELF_BYTES, x_neigh + bh * (NNB * FDIM),
                     NEIGH_BYTES, mb0);
    }

    int buf = 0;
    unsigned ph0 = 0, ph1 = 0;
    for (; bh < BH_TOTAL; bh += GRID) {
        // ---- Wait for current tile; all threads past previous tile ----
        if (buf == 0) { mbar_wait(mb0, ph0); ph0 ^= 1; }
        else          { mbar_wait(mb1, ph1); ph1 ^= 1; }
        __syncthreads();

        // ---- Prefetch next tile into other buffer ----
        const long nbh = bh + GRID;
        if (nbh < BH_TOTAL && tid == 0) {
            const unsigned nmb  = buf ? mb0 : mb1;
            const unsigned ndst = buf ? xsa0 : xsa1;
            mbar_expect_tx(nmb, TILE_BYTES);
            tma_bulk_g2s(ndst, x_self + nbh * FDIM, SELF_BYTES, nmb);
            tma_bulk_g2s(ndst + SELF_BYTES, x_neigh + nbh * (NNB * FDIM),
                         NEIGH_BYTES, nmb);
        }

        const float* xt = xs[buf];

        // ---- Scores: 27 warp-tasks over 16 warps, u in registers ----
        for (int task = warp; task < 27; task += 16) {   // warp-uniform trip count
            const int row = (task == 26) ? 0 : task;
            const float4 xv = ((const float4*)(xt + row * FDIM))[lane];
            const float4 uv = (task == 26) ? us4 : un4;
            const float s = xor_reduce(dot4(xv, uv));
            if (lane == 0) s_raw[task] = s;
        }
        __syncthreads();

        // ---- Softmax over 26 entries, redundantly per warp (no cross-warp dep) ----
        const float ss = s_raw[26];
        float v = (lane < KTOT) ? (ss + s_raw[lane]) : -3.0e38f;
        v = (v > 0.f) ? v : 0.2f * v;                    // leaky_relu(0.2)
        float m = v;
        #pragma unroll
        for (int o = 16; o; o >>= 1)
            m = fmaxf(m, __shfl_xor_sync(0xffffffffu, m, o));
        const float ex   = (lane < KTOT) ? __expf(v - m) : 0.f;
        const float inv  = 1.f / xor_reduce(ex);
        const float attn = ex * inv;                     // lane k holds weight k (0 for k>=26)

        // ---- Aggregate: quad-split over k. ALL shfls full-warp, no divergence ----
        // weights for the two tail entries, hoisted out of the predicated part:
        const float w24 = __shfl_sync(0xffffffffu, attn, 24);
        const float w25 = __shfl_sync(0xffffffffu, attn, 25);
        float acc = 0.f;
        #pragma unroll
        for (int jj = 0; jj < 6; jj++) {                 // k = 4*jj + g in [0,24)
            const int k = 4 * jj + g;
            const float wk = __shfl_sync(0xffffffffu, attn, k);  // uniform activity
            acc = fmaf(wk, xt[k * FDIM + d_own], acc);
        }
        if (g == 0) acc = fmaf(w24, xt[24 * FDIM + d_own], acc); // no shfl inside
        if (g == 1) acc = fmaf(w25, xt[25 * FDIM + d_own], acc);
        // in-quad reduction of the 4 partials (full-warp shfls)
        acc += __shfl_xor_sync(0xffffffffu, acc, 1);
        acc += __shfl_xor_sync(0xffffffffu, acc, 2);
        if (g == 0) xagg_sm[d_own] = acc;
        __syncthreads();

        // ---- Matvec vs register-resident W; bank-rotation conflict-free ----
        float r = 0.f;
        const float4* xa = (const float4*)(xagg_sm + 32 * g);
        #pragma unroll
        for (int i = 0; i < 8; i++) {
            const int ii = (i + 2 * g) & 7;
            const float4 vv = xa[ii];
            r = fmaf(vv.x, wreg[4 * ii + 0], r);
            r = fmaf(vv.y, wreg[4 * ii + 1], r);
            r = fmaf(vv.z, wreg[4 * ii + 2], r);
            r = fmaf(vv.w, wreg[4 * ii + 3], r);
        }
        r += __shfl_xor_sync(0xffffffffu, r, 1);
        r += __shfl_xor_sync(0xffffffffu, r, 2);
        if (g == 0)
            out[bh * DDIM + d_own] = fmaxf(r, 0.f);
        // no extra barrier: next iteration's post-wait __syncthreads orders
        // xagg_sm/s_raw reuse against this tile's readers.

        buf ^= 1;
    }
}

extern "C" void kernel_launch(void* const* d_in, const int* in_sizes, int n_in,
                              void* d_out, int out_size) {
    const float* x_self  = (const float*)d_in[0];
    const float* x_neigh = (const float*)d_in[1];
    const float* w_feat  = (const float*)d_in[2];
    const float* a_self  = (const float*)d_in[3];
    const float* a_neigh = (const float*)d_in[4];
    float* out = (float*)d_out;

    precompute_u_kernel<<<1, 256>>>(w_feat, a_self, a_neigh);
    gat_agg_kernel<<<GRID, NTHREADS>>>(x_self, x_neigh, w_feat, out);
}